// round 4
// baseline (speedup 1.0000x reference)
#include <cuda_runtime.h>
#include <cuda_bf16.h>
#include <math.h>

#define B 128
#define T 128
#define D 128
#define H 1024
#define TD (T*D)
#define JG 3072            // 3*H gate rows
#define SL (JG*B)          // slab elements per phase
#define NCTA 96
#define NTHR 256
#define SRW 40             // smem row stride (bf16 elems), ldmatrix conflict-free
#define STG_BYTES 15360    // per pipeline stage: W 64*40*2 + A 128*40*2

// ---------------------------------------------------------------------------
// Persistent scratch
// ---------------------------------------------------------------------------
__device__ __nv_bfloat16 g_w0cat[JG * 3 * D];     // W_ih0 split cat [hi|lo|hi]
__device__ __nv_bfloat16 g_wcat[5][JG * 3 * H];   // Whh0, Wih1, Whh1, Wih2, Whh2
__device__ __nv_bfloat16 g_hsplit[B * 2 * H];     // h split [b][hi|lo]
__device__ __nv_bfloat16 g_csplit[B * 2 * D];     // completed-input split
__device__ float g_h32[H * B];                    // fp32 hidden, [j][b]
__device__ float g_slab[2 * SL];                  // gi / gh partial sums
__device__ unsigned g_bar_count;
__device__ volatile unsigned g_bar_gen;

// ---------------------------------------------------------------------------
// Grid barrier: all-threads fence -> elect arrive -> spin on generation.
// __threadfence (gpu scope) emits CCTL.IVALL on sm_103a -> post-barrier loads
// see other CTAs' pre-barrier stores. Safe: 96 CTAs <= 148 SMs co-resident.
// ---------------------------------------------------------------------------
__device__ __forceinline__ void grid_barrier() {
    __threadfence();
    __syncthreads();
    if (threadIdx.x == 0) {
        unsigned gen = g_bar_gen;
        if (atomicAdd(&g_bar_count, 1) == NCTA - 1) {
            g_bar_count = 0;
            __threadfence();
            g_bar_gen = gen + 1;
        } else {
            while (g_bar_gen == gen) { __nanosleep(64); }
        }
        __threadfence();
    }
    __syncthreads();
}

// ---------------------------------------------------------------------------
// Weight split/cat: out[j][k]=hi, out[j][K+k]=lo, out[j][2K+k]=hi
// ---------------------------------------------------------------------------
__global__ void convert_w_kernel(const float* __restrict__ W, int dstid, int K) {
    int i = blockIdx.x * blockDim.x + threadIdx.x;
    int n = JG * K;
    if (i >= n) return;
    int j = i / K;
    int k = i - j * K;
    float f = W[i];
    __nv_bfloat16 hi = __float2bfloat16_rn(f);
    __nv_bfloat16 lo = __float2bfloat16_rn(f - __bfloat162float(hi));
    __nv_bfloat16* out = (dstid < 0) ? g_w0cat : g_wcat[dstid];
    size_t base = (size_t)j * 3 * K;
    out[base + k]         = hi;
    out[base + K + k]     = lo;
    out[base + 2 * K + k] = hi;
}

// ---------------------------------------------------------------------------
__global__ void init_kernel(const float* __restrict__ x) {
    int i = blockIdx.x * blockDim.x + threadIdx.x;
    if (i == 0) g_bar_count = 0;
    if (i < H * B) g_h32[i] = 0.0f;
    if (i < B * 2 * H) g_hsplit[i] = __float2bfloat16_rn(0.0f);
    if (i < B * D) {
        int d = i >> 7;
        int b = i & 127;
        float f = x[b * TD + d];
        __nv_bfloat16 hi = __float2bfloat16_rn(f);
        __nv_bfloat16 lo = __float2bfloat16_rn(f - __bfloat162float(hi));
        g_csplit[b * 2 * D + d]     = hi;
        g_csplit[b * 2 * D + D + d] = lo;
    }
}

// ---------------------------------------------------------------------------
// mma / ldmatrix / cp.async helpers
// ---------------------------------------------------------------------------
__device__ __forceinline__ void mma16816(float c[4], const unsigned a[4], const unsigned b[2]) {
    asm volatile(
        "mma.sync.aligned.m16n8k16.row.col.f32.bf16.bf16.f32 "
        "{%0,%1,%2,%3}, {%4,%5,%6,%7}, {%8,%9}, {%0,%1,%2,%3};"
        : "+f"(c[0]), "+f"(c[1]), "+f"(c[2]), "+f"(c[3])
        : "r"(a[0]), "r"(a[1]), "r"(a[2]), "r"(a[3]), "r"(b[0]), "r"(b[1]));
}
__device__ __forceinline__ void ldsm4(unsigned r[4], unsigned addr) {
    asm volatile("ldmatrix.sync.aligned.m8n8.x4.shared.b16 {%0,%1,%2,%3}, [%4];"
                 : "=r"(r[0]), "=r"(r[1]), "=r"(r[2]), "=r"(r[3]) : "r"(addr));
}
__device__ __forceinline__ void cpasync16(unsigned dst, const void* src) {
    asm volatile("cp.async.cg.shared.global [%0], [%1], 16;" :: "r"(dst), "l"(src));
}
__device__ __forceinline__ void cpcommit() { asm volatile("cp.async.commit_group;"); }

// ---------------------------------------------------------------------------
// One GEMM tile: slab[jg in j0..j0+63][0..127] = sum over 3 split-segs of
// W[jg][k] * A[b][k].  W cat width 3K (contiguous), A width 2K ([hi|lo]).
// 256 threads, warp tile 32x32, 3-stage cp.async pipeline.
// ---------------------------------------------------------------------------
__device__ void gemm_tile(
    const __nv_bfloat16* __restrict__ A, int astride, int K,
    const __nv_bfloat16* __restrict__ Wm, int wstride,
    float* __restrict__ slab, int j0, int tid, char* smem_raw)
{
    const int lane = tid & 31;
    const int wid  = tid >> 5;
    const int wj   = wid & 1;
    const int wb   = wid >> 1;
    const unsigned sbase = (unsigned)__cvta_generic_to_shared(smem_raw);
    const int S  = K >> 5;
    const int S3 = 3 * S;

    float acc[2][4][4];
    #pragma unroll
    for (int mi = 0; mi < 2; mi++)
        #pragma unroll
        for (int nb = 0; nb < 4; nb++)
            #pragma unroll
            for (int q = 0; q < 4; q++) acc[mi][nb][q] = 0.0f;

    auto stage = [&](int s) {
        int buf = s % 3;
        unsigned wdst = sbase + buf * STG_BYTES;
        unsigned bdst = wdst + 5120;
        int seg = s / S;
        int kk  = s - seg * S;
        int wcol = s * 32;
        int acol = ((seg == 2) ? K : 0) + kk * 32;
        #pragma unroll
        for (int p = 0; p < 3; p++) {
            int t = tid + (p << 8);
            if (t < 256) {
                int row = t >> 2, c = (t & 3) << 3;
                cpasync16(wdst + (row * SRW + c) * 2,
                          Wm + (size_t)(j0 + row) * wstride + wcol + c);
            } else {
                int t2 = t - 256;
                int row = t2 >> 2, c = (t2 & 3) << 3;
                cpasync16(bdst + (row * SRW + c) * 2,
                          A + (size_t)row * astride + acol + c);
            }
        }
        cpcommit();
    };

    stage(0);
    stage(1);
    for (int s = 0; s < S3; s++) {
        if (s + 2 < S3) { stage(s + 2); asm volatile("cp.async.wait_group 2;"); }
        else if (s + 1 < S3) { asm volatile("cp.async.wait_group 1;"); }
        else { asm volatile("cp.async.wait_group 0;"); }
        __syncthreads();

        const int buf = s % 3;
        const unsigned swb = sbase + buf * STG_BYTES;
        const unsigned sbb = swb + 5120;

        #pragma unroll
        for (int kkk = 0; kkk < 32; kkk += 16) {
            unsigned a0[4], a1[4], bfr[2][4];
            {
                int r = (lane & 15);
                int c = kkk + ((lane & 16) ? 8 : 0);
                ldsm4(a0, swb + ((wj * 32 +      r) * SRW + c) * 2);
                ldsm4(a1, swb + ((wj * 32 + 16 + r) * SRW + c) * 2);
            }
            #pragma unroll
            for (int nbp = 0; nbp < 2; nbp++) {
                int m = lane >> 3;
                int n = wb * 32 + nbp * 16 + ((m & 2) ? 8 : 0) + (lane & 7);
                int c = kkk + ((m & 1) ? 8 : 0);
                ldsm4(bfr[nbp], sbb + (n * SRW + c) * 2);
            }
            #pragma unroll
            for (int nbp = 0; nbp < 2; nbp++)
                #pragma unroll
                for (int hf = 0; hf < 2; hf++) {
                    int nb = nbp * 2 + hf;
                    mma16816(acc[0][nb], a0, &bfr[nbp][hf * 2]);
                    mma16816(acc[1][nb], a1, &bfr[nbp][hf * 2]);
                }
        }
        __syncthreads();
    }

    #pragma unroll
    for (int mi = 0; mi < 2; mi++)
        #pragma unroll
        for (int nb = 0; nb < 4; nb++) {
            int jg = j0 + wj * 32 + mi * 16 + (lane >> 2);
            int b  = wb * 32 + nb * 8 + ((lane & 3) << 1);
            *(float2*)(slab + (size_t)jg * B + b)       = make_float2(acc[mi][nb][0], acc[mi][nb][1]);
            *(float2*)(slab + (size_t)(jg + 8) * B + b) = make_float2(acc[mi][nb][2], acc[mi][nb][3]);
        }
}

// ---------------------------------------------------------------------------
// THE persistent kernel: whole T loop. grid NCTA x NTHR.
// ---------------------------------------------------------------------------
__global__ __launch_bounds__(NTHR) void persistent_kernel(
    const float* __restrict__ x, const float* __restrict__ masks,
    const float* __restrict__ b_ih0, const float* __restrict__ b_hh0,
    const float* __restrict__ b_ih_r, const float* __restrict__ b_hh_r,
    const float* __restrict__ Wp, const float* __restrict__ bp,
    float* __restrict__ out_h,
    float* __restrict__ out_completed,
    float* __restrict__ out_imputed)
{
    __shared__ __align__(16) char smem_raw[3 * STG_BYTES];

    const int tid   = threadIdx.x;
    const int cta   = blockIdx.x;
    const int phase = cta / 48;          // 0 = gi (input side), 1 = gh (hidden side)
    const int jt    = cta - phase * 48;

    for (int t = 0; t < T; t++) {
        // ------- three GRU layers -------
        for (int l = 0; l < 3; l++) {
            const __nv_bfloat16* A;
            const __nv_bfloat16* Wm;
            int astride, K, wstride;
            if (phase == 0) {
                if (l == 0) { A = g_csplit; astride = 2 * D; K = D; Wm = g_w0cat; wstride = 3 * D; }
                else        { A = g_hsplit; astride = 2 * H; K = H; Wm = g_wcat[2 * l - 1]; wstride = 3 * H; }
            } else {
                A = g_hsplit; astride = 2 * H; K = H;
                Wm = (l == 0) ? g_wcat[0] : g_wcat[2 * l];
                wstride = 3 * H;
            }
            gemm_tile(A, astride, K, Wm, wstride,
                      g_slab + (size_t)phase * SL, jt * 64, tid, smem_raw);
            grid_barrier();

            // epilogue: reduce 2 slabs + GRU pointwise, in-place h32, hsplit
            const float* bi = (l == 0) ? b_ih0 : b_ih_r + (size_t)(l - 1) * JG;
            const float* bh = (l == 0) ? b_hh0 : b_hh_r + (size_t)(l - 1) * JG;
            for (int i = cta * NTHR + tid; i < H * B; i += NCTA * NTHR) {
                int b = i & 127;
                int j = i >> 7;
                float gi[3], gh[3];
                #pragma unroll
                for (int g = 0; g < 3; g++) {
                    int r = (g << 10) + j;
                    size_t o = (size_t)r * B + b;
                    gi[g] = g_slab[o] + bi[r];
                    gh[g] = g_slab[SL + o] + bh[r];
                }
                float hp = g_h32[j * B + b];
                float rg = 1.0f / (1.0f + expf(-(gi[0] + gh[0])));
                float zg = 1.0f / (1.0f + expf(-(gi[1] + gh[1])));
                float ng = tanhf(gi[2] + rg * gh[2]);
                float hn = (1.0f - zg) * ng + zg * hp;
                g_h32[j * B + b] = hn;
                __nv_bfloat16 hi = __float2bfloat16_rn(hn);
                __nv_bfloat16 lo = __float2bfloat16_rn(hn - __bfloat162float(hi));
                g_hsplit[b * 2 * H + j]     = hi;
                g_hsplit[b * 2 * H + H + j] = lo;
            }
            grid_barrier();
        }

        // ------- projection + masking (CTAs 0..63) -------
        if (cta < 64) {
            float* sH  = (float*)smem_raw;            // 32*68
            float* sWp = (float*)smem_raw + 32 * 68;  // 32*4
            const int bt = tid & 63;
            const int dt = tid >> 6;
            const int b0 = (cta & 1) * 64;
            const int d0 = (cta >> 1) * 4;

            float acc = 0.0f;
            for (int k0 = 0; k0 < H; k0 += 32) {
                __syncthreads();
                #pragma unroll
                for (int i = tid; i < 32 * 16; i += NTHR) {
                    int kr = i >> 4;
                    int bq = i & 15;
                    float4 v = *(const float4*)(g_h32 + (k0 + kr) * B + b0 + bq * 4);
                    *(float4*)(sH + kr * 68 + bq * 4) = v;
                }
                if (tid < 32) {
                    int slot = tid >> 3;
                    int q    = tid & 7;
                    const float4 v = *(const float4*)(Wp + (size_t)(d0 + slot) * H + k0 + q * 4);
                    sWp[(q * 4 + 0) * 4 + slot] = v.x;
                    sWp[(q * 4 + 1) * 4 + slot] = v.y;
                    sWp[(q * 4 + 2) * 4 + slot] = v.z;
                    sWp[(q * 4 + 3) * 4 + slot] = v.w;
                }
                __syncthreads();
                #pragma unroll
                for (int k = 0; k < 32; k++)
                    acc += sH[k * 68 + bt] * sWp[k * 4 + dt];
            }

            const int d = d0 + dt;
            const int b = b0 + bt;
            float imp = acc + bp[d];
            float m  = masks[b * T + t];
            float xv = x[b * TD + t * D + d];
            float c  = m * xv + (1.0f - m) * imp;
            __nv_bfloat16 hi = __float2bfloat16_rn(c);
            __nv_bfloat16 lo = __float2bfloat16_rn(c - __bfloat162float(hi));
            g_csplit[b * 2 * D + d]     = hi;
            g_csplit[b * 2 * D + D + d] = lo;
            if (t < T - 1) {
                int base = b * (T - 1) * D + t * D + d;
                out_completed[base] = c;
                out_imputed[base]   = imp;
            }
        }
        grid_barrier();
    }

    // ------- final hidden state: out[b*H + j] = h32[j][b] -------
    for (int i = cta * NTHR + tid; i < H * B; i += NCTA * NTHR) {
        int b = i >> 10;
        int j = i & 1023;
        out_h[i] = g_h32[j * B + b];
    }
}

// ---------------------------------------------------------------------------
extern "C" void kernel_launch(void* const* d_in, const int* in_sizes, int n_in,
                              void* d_out, int out_size) {
    const float* x      = (const float*)d_in[0];
    const float* masks  = (const float*)d_in[1];
    const float* W_ih0  = (const float*)d_in[2];
    const float* W_hh0  = (const float*)d_in[3];
    const float* b_ih0  = (const float*)d_in[4];
    const float* b_hh0  = (const float*)d_in[5];
    const float* W_ih_r = (const float*)d_in[6];
    const float* W_hh_r = (const float*)d_in[7];
    const float* b_ih_r = (const float*)d_in[8];
    const float* b_hh_r = (const float*)d_in[9];
    const float* Wp     = (const float*)d_in[10];
    const float* bp     = (const float*)d_in[11];

    float* out = (float*)d_out;
    float* out_h         = out;
    float* out_completed = out + H * B;
    float* out_imputed   = out_completed + (size_t)B * (T - 1) * D;

    {
        int n0 = JG * D;
        convert_w_kernel<<<(n0 + 255) / 256, 256>>>(W_ih0, -1, D);
        int n1 = JG * H;
        convert_w_kernel<<<(n1 + 255) / 256, 256>>>(W_hh0, 0, H);
        convert_w_kernel<<<(n1 + 255) / 256, 256>>>(W_ih_r,                  1, H);
        convert_w_kernel<<<(n1 + 255) / 256, 256>>>(W_hh_r,                  2, H);
        convert_w_kernel<<<(n1 + 255) / 256, 256>>>(W_ih_r + (size_t)JG * H, 3, H);
        convert_w_kernel<<<(n1 + 255) / 256, 256>>>(W_hh_r + (size_t)JG * H, 4, H);
    }

    init_kernel<<<(B * 2 * H + 255) / 256, 256>>>(x);

    persistent_kernel<<<NCTA, NTHR>>>(
        x, masks, b_ih0, b_hh0, b_ih_r, b_hh_r, Wp, bp,
        out_h, out_completed, out_imputed);
}